// round 2
// baseline (speedup 1.0000x reference)
#include <cuda_runtime.h>
#include <cuda_bf16.h>

#define N_NODES 100000
#define E_EDGES 1600000
#define HID     64
#define IN_C    128
#define OUT_F   25
#define NCHUNK  98   // ceil(N/1024)

// ---------------- device scratch (static: no allocations allowed) ----------
__device__ int   g_count[N_NODES];      // degree counts, later scatter cursor
__device__ float g_dinv [N_NODES];      // rsqrt(deg+1)
__device__ int   g_off  [N_NODES + 1];  // CSR offsets (by col)
__device__ int   g_bsum [128];          // scan block sums
__device__ int   g_src  [E_EDGES];      // row indices sorted by col
__device__ float g_h    [N_NODES * HID]; // h = x @ W
__device__ float g_x    [N_NODES * HID]; // activations between layers
__device__ float g_pool [HID];

// ---------------- init ------------------------------------------------------
__global__ void zero_kernel() {
    int i = blockIdx.x * 256 + threadIdx.x;
    if (i < N_NODES) g_count[i] = 0;
    if (i < HID)     g_pool[i]  = 0.f;
}

__global__ void count_kernel(const int* __restrict__ col) {
    int e = blockIdx.x * 256 + threadIdx.x;
    if (e < E_EDGES) atomicAdd(&g_count[col[e]], 1);
}

// exclusive scan of g_count into g_off  (3-phase: block scan, scan of sums, add)
__global__ void scan1_kernel() {
    __shared__ int sh[256];
    int b = blockIdx.x, t = threadIdx.x;
    int base = b * 1024 + t * 4;
    int v0 = (base + 0 < N_NODES) ? g_count[base + 0] : 0;
    int v1 = (base + 1 < N_NODES) ? g_count[base + 1] : 0;
    int v2 = (base + 2 < N_NODES) ? g_count[base + 2] : 0;
    int v3 = (base + 3 < N_NODES) ? g_count[base + 3] : 0;
    int tot = v0 + v1 + v2 + v3;
    sh[t] = tot;
    __syncthreads();
    for (int o = 1; o < 256; o <<= 1) {
        int x = (t >= o) ? sh[t - o] : 0;
        __syncthreads();
        sh[t] += x;
        __syncthreads();
    }
    int excl = sh[t] - tot;
    if (base + 0 < N_NODES) g_off[base + 0] = excl;
    if (base + 1 < N_NODES) g_off[base + 1] = excl + v0;
    if (base + 2 < N_NODES) g_off[base + 2] = excl + v0 + v1;
    if (base + 3 < N_NODES) g_off[base + 3] = excl + v0 + v1 + v2;
    if (t == 255) g_bsum[b] = sh[255];
}

__global__ void scan2_kernel(int nb) {
    if (threadIdx.x == 0 && blockIdx.x == 0) {
        int run = 0;
        for (int b = 0; b < nb; b++) { int x = g_bsum[b]; g_bsum[b] = run; run += x; }
        g_off[N_NODES] = run;   // == E
    }
}

__global__ void scan3_kernel() {
    int b = blockIdx.x;
    int add = g_bsum[b];
    int base = b * 1024 + threadIdx.x * 4;
#pragma unroll
    for (int i = 0; i < 4; i++)
        if (base + i < N_NODES) g_off[base + i] += add;
}

// dinv from counts, then reset counts so they can serve as scatter cursors
__global__ void dinv_reset_kernel() {
    int v = blockIdx.x * 256 + threadIdx.x;
    if (v < N_NODES) {
        g_dinv[v] = rsqrtf((float)g_count[v] + 1.0f);
        g_count[v] = 0;
    }
}

__global__ void scatter_kernel(const int* __restrict__ row, const int* __restrict__ col) {
    int e = blockIdx.x * 256 + threadIdx.x;
    if (e < E_EDGES) {
        int c = col[e];
        int pos = g_off[c] + atomicAdd(&g_count[c], 1);
        g_src[pos] = row[e];
    }
}

// ---------------- GEMM: H[n][0..63] = X[n][0..K-1] @ W[K][64] ---------------
template <int K>
__global__ void __launch_bounds__(128)
gemm_kernel(const float* __restrict__ X, const float* __restrict__ W,
            float* __restrict__ H) {
    __shared__ float Ws[K * HID];
    for (int i = threadIdx.x; i < K * HID; i += 128) Ws[i] = W[i];
    __syncthreads();
    int n = blockIdx.x * 128 + threadIdx.x;
    if (n >= N_NODES) return;

    float acc[HID];
#pragma unroll
    for (int j = 0; j < HID; j++) acc[j] = 0.f;

    const float4* xr = reinterpret_cast<const float4*>(X + (size_t)n * K);
#pragma unroll 2
    for (int k4 = 0; k4 < K / 4; k4++) {
        float4 xv = xr[k4];
        float xs[4] = {xv.x, xv.y, xv.z, xv.w};
#pragma unroll
        for (int kk = 0; kk < 4; kk++) {
            float xval = xs[kk];
            const float4* wr = reinterpret_cast<const float4*>(&Ws[(k4 * 4 + kk) * HID]);
#pragma unroll
            for (int j4 = 0; j4 < HID / 4; j4++) {
                float4 w = wr[j4];
                acc[j4 * 4 + 0] += xval * w.x;
                acc[j4 * 4 + 1] += xval * w.y;
                acc[j4 * 4 + 2] += xval * w.z;
                acc[j4 * 4 + 3] += xval * w.w;
            }
        }
    }
    float4* out = reinterpret_cast<float4*>(H + (size_t)n * HID);
#pragma unroll
    for (int j4 = 0; j4 < HID / 4; j4++)
        out[j4] = make_float4(acc[j4 * 4], acc[j4 * 4 + 1], acc[j4 * 4 + 2], acc[j4 * 4 + 3]);
}

// ------- fused: CSR gather-aggregate + self-loop + bias + LN + ReLU ---------
// one warp per node; lane l owns features 2l, 2l+1 (float2, coalesced)
__global__ void __launch_bounds__(256)
agg_ln_kernel(const float* __restrict__ H, const float* __restrict__ bias,
              const float* __restrict__ lnw, const float* __restrict__ lnb,
              float* __restrict__ Xo) {
    int v = (blockIdx.x * 256 + threadIdx.x) >> 5;
    int lane = threadIdx.x & 31;
    if (v >= N_NODES) return;

    int beg = g_off[v], end = g_off[v + 1];
    const float2* H2 = reinterpret_cast<const float2*>(H);

    float ax = 0.f, ay = 0.f;
    int e = beg;
    for (; e + 2 <= end; e += 2) {            // 2-wide for MLP
        int s0 = g_src[e], s1 = g_src[e + 1];
        float w0 = g_dinv[s0], w1 = g_dinv[s1];
        float2 h0 = H2[(size_t)s0 * 32 + lane];
        float2 h1 = H2[(size_t)s1 * 32 + lane];
        ax += w0 * h0.x + w1 * h1.x;
        ay += w0 * h0.y + w1 * h1.y;
    }
    if (e < end) {
        int s = g_src[e];
        float w = g_dinv[s];
        float2 h = H2[(size_t)s * 32 + lane];
        ax += w * h.x; ay += w * h.y;
    }

    float dv = g_dinv[v];
    float2 hs = H2[(size_t)v * 32 + lane];
    ax = ax * dv + dv * dv * hs.x + bias[lane * 2 + 0];
    ay = ay * dv + dv * dv * hs.y + bias[lane * 2 + 1];

    // LayerNorm over 64 features (warp reduce)
    float sum = ax + ay;
    float sq  = ax * ax + ay * ay;
#pragma unroll
    for (int o = 16; o > 0; o >>= 1) {
        sum += __shfl_xor_sync(0xffffffffu, sum, o);
        sq  += __shfl_xor_sync(0xffffffffu, sq,  o);
    }
    float mu  = sum * (1.f / 64.f);
    float var = sq * (1.f / 64.f) - mu * mu;
    float r   = rsqrtf(var + 1e-5f);
    float y0 = (ax - mu) * r * lnw[lane * 2 + 0] + lnb[lane * 2 + 0];
    float y1 = (ay - mu) * r * lnw[lane * 2 + 1] + lnb[lane * 2 + 1];
    float2 o2;
    o2.x = fmaxf(y0, 0.f);
    o2.y = fmaxf(y1, 0.f);
    reinterpret_cast<float2*>(Xo)[(size_t)v * 32 + lane] = o2;
}

// ---------------- pooling + linear head -------------------------------------
__global__ void pool_kernel(const float* __restrict__ X) {
    __shared__ float sh[256];
    int j = threadIdx.x & 63;
    int g = threadIdx.x >> 6;
    float s = 0.f;
    for (int v = blockIdx.x * 4 + g; v < N_NODES; v += gridDim.x * 4)
        s += X[(size_t)v * 64 + j];
    sh[threadIdx.x] = s;
    __syncthreads();
    if (threadIdx.x < 64)
        atomicAdd(&g_pool[j], sh[threadIdx.x] + sh[threadIdx.x + 64] +
                               sh[threadIdx.x + 128] + sh[threadIdx.x + 192]);
}

__global__ void final_kernel(const float* __restrict__ Wl, const float* __restrict__ bl,
                             float* __restrict__ out) {
    int o = threadIdx.x;
    if (o < OUT_F) {
        float s = 0.f;
#pragma unroll
        for (int j = 0; j < HID; j++) s += g_pool[j] * Wl[j * OUT_F + o];
        out[o] = s * (1.0f / N_NODES) + bl[o];
    }
}

// ---------------- launch ----------------------------------------------------
extern "C" void kernel_launch(void* const* d_in, const int* in_sizes, int n_in,
                              void* d_out, int out_size) {
    const float* x    = (const float*)d_in[0];
    const int*   ei   = (const int*)  d_in[1];
    const float* W1   = (const float*)d_in[2];
    const float* b1   = (const float*)d_in[3];
    const float* W2   = (const float*)d_in[4];
    const float* b2   = (const float*)d_in[5];
    const float* W3   = (const float*)d_in[6];
    const float* b3   = (const float*)d_in[7];
    const float* ln1w = (const float*)d_in[8];
    const float* ln1b = (const float*)d_in[9];
    const float* ln2w = (const float*)d_in[10];
    const float* ln2b = (const float*)d_in[11];
    const float* ln3w = (const float*)d_in[12];
    const float* ln3b = (const float*)d_in[13];
    const float* Wl   = (const float*)d_in[14];
    const float* bl   = (const float*)d_in[15];
    float* out = (float*)d_out;

    const int* row = ei;            // edge_index[0]
    const int* col = ei + E_EDGES;  // edge_index[1]

    float* gh = nullptr; cudaGetSymbolAddress((void**)&gh, g_h);
    float* gx = nullptr; cudaGetSymbolAddress((void**)&gx, g_x);

    int nB  = (N_NODES + 255) / 256;   // 391
    int eB  = (E_EDGES + 255) / 256;   // 6250
    int gB1 = (N_NODES + 127) / 128;   // 782
    int aB  = (N_NODES * 32 + 255) / 256; // 12500 (warp/node)

    zero_kernel<<<nB, 256>>>();
    count_kernel<<<eB, 256>>>(col);
    scan1_kernel<<<NCHUNK, 256>>>();
    scan2_kernel<<<1, 32>>>(NCHUNK);
    scan3_kernel<<<NCHUNK, 256>>>();
    dinv_reset_kernel<<<nB, 256>>>();
    scatter_kernel<<<eB, 256>>>(row, col);

    // layer 1: x[128] -> h -> agg/LN/ReLU -> g_x
    gemm_kernel<IN_C><<<gB1, 128>>>(x, W1, gh);
    agg_ln_kernel<<<aB, 256>>>(gh, b1, ln1w, ln1b, gx);
    // layer 2
    gemm_kernel<HID><<<gB1, 128>>>(gx, W2, gh);
    agg_ln_kernel<<<aB, 256>>>(gh, b2, ln2w, ln2b, gx);
    // layer 3
    gemm_kernel<HID><<<gB1, 128>>>(gx, W3, gh);
    agg_ln_kernel<<<aB, 256>>>(gh, b3, ln3w, ln3b, gx);

    pool_kernel<<<512, 256>>>(gx);
    final_kernel<<<1, 32>>>(Wl, bl, out);
}

// round 3
// speedup vs baseline: 1.6308x; 1.6308x over previous
#include <cuda_runtime.h>
#include <cuda_bf16.h>

#define N_NODES 100000
#define E_EDGES 1600000
#define HID     64
#define IN_C    128
#define OUT_F   25
#define NCHUNK  98   // ceil(N/1024)

// ---------------- device scratch (static: no allocations allowed) ----------
__device__ int   g_count[N_NODES];      // degree counts, later scatter cursor
__device__ float g_dinv [N_NODES];      // rsqrt(deg+1)
__device__ int   g_off  [N_NODES + 1];  // CSR offsets (by col)
__device__ int   g_bsum [128];          // scan block sums
__device__ int   g_src  [E_EDGES];      // row indices sorted by col
__device__ float g_h    [N_NODES * HID]; // Hs = dinv*(x@W), stored as bf16 (reinterpreted)
__device__ float g_x    [N_NODES * HID]; // fp32 activations between layers
__device__ float g_pool [HID];

// ---------------- init ------------------------------------------------------
__global__ void zero_kernel() {
    int i = blockIdx.x * 256 + threadIdx.x;
    if (i < N_NODES) g_count[i] = 0;
    if (i < HID)     g_pool[i]  = 0.f;
}

__global__ void count_kernel(const int* __restrict__ col) {
    int e = blockIdx.x * 256 + threadIdx.x;
    if (e < E_EDGES) atomicAdd(&g_count[col[e]], 1);
}

// exclusive scan of g_count into g_off  (3-phase)
__global__ void scan1_kernel() {
    __shared__ int sh[256];
    int b = blockIdx.x, t = threadIdx.x;
    int base = b * 1024 + t * 4;
    int v0 = (base + 0 < N_NODES) ? g_count[base + 0] : 0;
    int v1 = (base + 1 < N_NODES) ? g_count[base + 1] : 0;
    int v2 = (base + 2 < N_NODES) ? g_count[base + 2] : 0;
    int v3 = (base + 3 < N_NODES) ? g_count[base + 3] : 0;
    int tot = v0 + v1 + v2 + v3;
    sh[t] = tot;
    __syncthreads();
    for (int o = 1; o < 256; o <<= 1) {
        int x = (t >= o) ? sh[t - o] : 0;
        __syncthreads();
        sh[t] += x;
        __syncthreads();
    }
    int excl = sh[t] - tot;
    if (base + 0 < N_NODES) g_off[base + 0] = excl;
    if (base + 1 < N_NODES) g_off[base + 1] = excl + v0;
    if (base + 2 < N_NODES) g_off[base + 2] = excl + v0 + v1;
    if (base + 3 < N_NODES) g_off[base + 3] = excl + v0 + v1 + v2;
    if (t == 255) g_bsum[b] = sh[255];
}

__global__ void scan2_kernel() {
    __shared__ int sh[128];
    int t = threadIdx.x;
    int v = (t < NCHUNK) ? g_bsum[t] : 0;
    sh[t] = v;
    __syncthreads();
    for (int o = 1; o < 128; o <<= 1) {
        int x = (t >= o) ? sh[t - o] : 0;
        __syncthreads();
        sh[t] += x;
        __syncthreads();
    }
    if (t < NCHUNK) g_bsum[t] = sh[t] - v;   // exclusive
    if (t == 127)   g_off[N_NODES] = sh[127];
}

__global__ void scan3_kernel() {
    int b = blockIdx.x;
    int add = g_bsum[b];
    int base = b * 1024 + threadIdx.x * 4;
#pragma unroll
    for (int i = 0; i < 4; i++)
        if (base + i < N_NODES) g_off[base + i] += add;
}

// dinv from counts, then reset counts so they can serve as scatter cursors
__global__ void dinv_reset_kernel() {
    int v = blockIdx.x * 256 + threadIdx.x;
    if (v < N_NODES) {
        g_dinv[v] = rsqrtf((float)g_count[v] + 1.0f);
        g_count[v] = 0;
    }
}

__global__ void scatter_kernel(const int* __restrict__ row, const int* __restrict__ col) {
    int e = blockIdx.x * 256 + threadIdx.x;
    if (e < E_EDGES) {
        int c = col[e];
        int pos = g_off[c] + atomicAdd(&g_count[c], 1);
        g_src[pos] = row[e];
    }
}

// ---------------- GEMM: Hs[n] = dinv[n] * (X[n] @ W), bf16 output -----------
// packed f32x2 FFMA (2x fp32 MAC throughput; ptxas never emits this itself)
template <int K>
__global__ void __launch_bounds__(128)
gemm_kernel(const float* __restrict__ X, const float* __restrict__ W,
            __nv_bfloat162* __restrict__ Hs) {
    __shared__ float Ws[K * HID];
    for (int i = threadIdx.x; i < K * HID; i += 128) Ws[i] = W[i];
    __syncthreads();
    int n = blockIdx.x * 128 + threadIdx.x;
    if (n >= N_NODES) return;

    unsigned long long acc[32];
#pragma unroll
    for (int j = 0; j < 32; j++) acc[j] = 0ull;   // {+0.f, +0.f}

    const float4* xr = reinterpret_cast<const float4*>(X + (size_t)n * K);
#pragma unroll 1
    for (int k4 = 0; k4 < K / 4; k4++) {
        float4 xv = xr[k4];
        float xs[4] = {xv.x, xv.y, xv.z, xv.w};
#pragma unroll
        for (int kk = 0; kk < 4; kk++) {
            unsigned long long xx;
            asm("mov.b64 %0, {%1, %1};" : "=l"(xx) : "f"(xs[kk]));
            const ulonglong2* wr =
                reinterpret_cast<const ulonglong2*>(&Ws[(k4 * 4 + kk) * HID]);
#pragma unroll
            for (int j = 0; j < 16; j++) {
                ulonglong2 w = wr[j];
                asm("fma.rn.f32x2 %0, %1, %2, %0;" : "+l"(acc[2 * j])     : "l"(xx), "l"(w.x));
                asm("fma.rn.f32x2 %0, %1, %2, %0;" : "+l"(acc[2 * j + 1]) : "l"(xx), "l"(w.y));
            }
        }
    }
    float dv = g_dinv[n];
    unsigned int out32[32];
#pragma unroll
    for (int j = 0; j < 32; j++) {
        float2 f = *reinterpret_cast<float2*>(&acc[j]);
        __nv_bfloat162 b = __float22bfloat162_rn(make_float2(f.x * dv, f.y * dv));
        out32[j] = *reinterpret_cast<unsigned int*>(&b);
    }
    uint4* o = reinterpret_cast<uint4*>(Hs + (size_t)n * 32);
#pragma unroll
    for (int j = 0; j < 8; j++)
        o[j] = make_uint4(out32[4 * j], out32[4 * j + 1], out32[4 * j + 2], out32[4 * j + 3]);
}

// ------- fused: CSR gather-aggregate + self-loop + bias + LN + ReLU ---------
// one warp per node; lane l owns features 2l, 2l+1 (bf16x2 read, fp32 math)
__global__ void __launch_bounds__(256)
agg_ln_kernel(const __nv_bfloat162* __restrict__ H2, const float* __restrict__ bias,
              const float* __restrict__ lnw, const float* __restrict__ lnb,
              float* __restrict__ Xo) {
    int v = (blockIdx.x * 256 + threadIdx.x) >> 5;
    int lane = threadIdx.x & 31;
    if (v >= N_NODES) return;

    int beg = g_off[v], end = g_off[v + 1];

    float ax = 0.f, ay = 0.f;
    int e = beg;
    for (; e + 4 <= end; e += 4) {
        int s0 = g_src[e], s1 = g_src[e + 1], s2 = g_src[e + 2], s3 = g_src[e + 3];
        float2 h0 = __bfloat1622float2(H2[(size_t)s0 * 32 + lane]);
        float2 h1 = __bfloat1622float2(H2[(size_t)s1 * 32 + lane]);
        float2 h2 = __bfloat1622float2(H2[(size_t)s2 * 32 + lane]);
        float2 h3 = __bfloat1622float2(H2[(size_t)s3 * 32 + lane]);
        ax += (h0.x + h1.x) + (h2.x + h3.x);
        ay += (h0.y + h1.y) + (h2.y + h3.y);
    }
    for (; e < end; e++) {
        int s = g_src[e];
        float2 h = __bfloat1622float2(H2[(size_t)s * 32 + lane]);
        ax += h.x; ay += h.y;
    }

    float dv = g_dinv[v];
    float2 hs = __bfloat1622float2(H2[(size_t)v * 32 + lane]);
    // Hs already carries dinv[src]; total = dv*(sum_neighbors + self)
    ax = (ax + hs.x) * dv + bias[lane * 2 + 0];
    ay = (ay + hs.y) * dv + bias[lane * 2 + 1];

    // LayerNorm over 64 features (warp reduce)
    float sum = ax + ay;
    float sq  = ax * ax + ay * ay;
#pragma unroll
    for (int o = 16; o > 0; o >>= 1) {
        sum += __shfl_xor_sync(0xffffffffu, sum, o);
        sq  += __shfl_xor_sync(0xffffffffu, sq,  o);
    }
    float mu  = sum * (1.f / 64.f);
    float var = sq * (1.f / 64.f) - mu * mu;
    float r   = rsqrtf(var + 1e-5f);
    float y0 = (ax - mu) * r * lnw[lane * 2 + 0] + lnb[lane * 2 + 0];
    float y1 = (ay - mu) * r * lnw[lane * 2 + 1] + lnb[lane * 2 + 1];
    float2 o2;
    o2.x = fmaxf(y0, 0.f);
    o2.y = fmaxf(y1, 0.f);
    reinterpret_cast<float2*>(Xo)[(size_t)v * 32 + lane] = o2;
}

// ---------------- pooling + linear head -------------------------------------
__global__ void pool_kernel(const float* __restrict__ X) {
    __shared__ float sh[256];
    int j = threadIdx.x & 63;
    int g = threadIdx.x >> 6;
    float s = 0.f;
    for (int v = blockIdx.x * 4 + g; v < N_NODES; v += gridDim.x * 4)
        s += X[(size_t)v * 64 + j];
    sh[threadIdx.x] = s;
    __syncthreads();
    if (threadIdx.x < 64)
        atomicAdd(&g_pool[j], sh[threadIdx.x] + sh[threadIdx.x + 64] +
                               sh[threadIdx.x + 128] + sh[threadIdx.x + 192]);
}

__global__ void final_kernel(const float* __restrict__ Wl, const float* __restrict__ bl,
                             float* __restrict__ out) {
    int o = threadIdx.x;
    if (o < OUT_F) {
        float s = 0.f;
#pragma unroll
        for (int j = 0; j < HID; j++) s += g_pool[j] * Wl[j * OUT_F + o];
        out[o] = s * (1.0f / N_NODES) + bl[o];
    }
}

// ---------------- launch ----------------------------------------------------
extern "C" void kernel_launch(void* const* d_in, const int* in_sizes, int n_in,
                              void* d_out, int out_size) {
    const float* x    = (const float*)d_in[0];
    const int*   ei   = (const int*)  d_in[1];
    const float* W1   = (const float*)d_in[2];
    const float* b1   = (const float*)d_in[3];
    const float* W2   = (const float*)d_in[4];
    const float* b2   = (const float*)d_in[5];
    const float* W3   = (const float*)d_in[6];
    const float* b3   = (const float*)d_in[7];
    const float* ln1w = (const float*)d_in[8];
    const float* ln1b = (const float*)d_in[9];
    const float* ln2w = (const float*)d_in[10];
    const float* ln2b = (const float*)d_in[11];
    const float* ln3w = (const float*)d_in[12];
    const float* ln3b = (const float*)d_in[13];
    const float* Wl   = (const float*)d_in[14];
    const float* bl   = (const float*)d_in[15];
    float* out = (float*)d_out;

    const int* row = ei;            // edge_index[0]
    const int* col = ei + E_EDGES;  // edge_index[1]

    __nv_bfloat162* gh = nullptr; cudaGetSymbolAddress((void**)&gh, g_h);
    float*          gx = nullptr; cudaGetSymbolAddress((void**)&gx, g_x);

    int nB  = (N_NODES + 255) / 256;        // 391
    int eB  = (E_EDGES + 255) / 256;        // 6250
    int gB1 = (N_NODES + 127) / 128;        // 782
    int aB  = (N_NODES * 32 + 255) / 256;   // 12500 (warp/node)

    zero_kernel<<<nB, 256>>>();
    count_kernel<<<eB, 256>>>(col);
    scan1_kernel<<<NCHUNK, 256>>>();
    scan2_kernel<<<1, 128>>>();
    scan3_kernel<<<NCHUNK, 256>>>();
    dinv_reset_kernel<<<nB, 256>>>();
    scatter_kernel<<<eB, 256>>>(row, col);

    // layer 1: x[128] -> Hs(bf16) -> agg/LN/ReLU -> g_x (fp32)
    gemm_kernel<IN_C><<<gB1, 128>>>(x, W1, gh);
    agg_ln_kernel<<<aB, 256>>>(gh, b1, ln1w, ln1b, gx);
    // layer 2
    gemm_kernel<HID><<<gB1, 128>>>(gx, W2, gh);
    agg_ln_kernel<<<aB, 256>>>(gh, b2, ln2w, ln2b, gx);
    // layer 3
    gemm_kernel<HID><<<gB1, 128>>>(gx, W3, gh);
    agg_ln_kernel<<<aB, 256>>>(gh, b3, ln3w, ln3b, gx);

    pool_kernel<<<512, 256>>>(gx);
    final_kernel<<<1, 32>>>(Wl, bl, out);
}

// round 4
// speedup vs baseline: 1.7157x; 1.0521x over previous
#include <cuda_runtime.h>
#include <cuda_bf16.h>

#define N_NODES 100000
#define E_EDGES 1600000
#define HID     64
#define IN_C    128
#define OUT_F   25
#define NCHUNK  98   // ceil(N/1024)

// ---------------- device scratch (static: no allocations allowed) ----------
__device__ int   g_count[N_NODES];      // degree counts, later scatter cursor
__device__ float g_dinv [N_NODES];      // rsqrt(deg+1)
__device__ int   g_off  [N_NODES + 1];  // CSR offsets (by col)
__device__ int   g_bsum [128];          // scan block sums
__device__ int   g_src  [E_EDGES];      // row indices sorted by col
__device__ float g_h    [N_NODES * HID]; // Hs bf16 (reinterpreted), dinv-scaled
__device__ float g_x    [N_NODES * HID]; // fp32 activations between layers
__device__ float g_pool [HID];

// ---------------- CSR build --------------------------------------------------
__global__ void count_kernel(const int* __restrict__ col) {
    int e = blockIdx.x * 256 + threadIdx.x;
    if (e < E_EDGES) atomicAdd(&g_count[col[e]], 1);
}

// exclusive scan of g_count into g_off  (3-phase)
__global__ void scan1_kernel() {
    __shared__ int sh[256];
    int b = blockIdx.x, t = threadIdx.x;
    int base = b * 1024 + t * 4;
    int v0 = (base + 0 < N_NODES) ? g_count[base + 0] : 0;
    int v1 = (base + 1 < N_NODES) ? g_count[base + 1] : 0;
    int v2 = (base + 2 < N_NODES) ? g_count[base + 2] : 0;
    int v3 = (base + 3 < N_NODES) ? g_count[base + 3] : 0;
    int tot = v0 + v1 + v2 + v3;
    sh[t] = tot;
    __syncthreads();
    for (int o = 1; o < 256; o <<= 1) {
        int x = (t >= o) ? sh[t - o] : 0;
        __syncthreads();
        sh[t] += x;
        __syncthreads();
    }
    int excl = sh[t] - tot;
    if (base + 0 < N_NODES) g_off[base + 0] = excl;
    if (base + 1 < N_NODES) g_off[base + 1] = excl + v0;
    if (base + 2 < N_NODES) g_off[base + 2] = excl + v0 + v1;
    if (base + 3 < N_NODES) g_off[base + 3] = excl + v0 + v1 + v2;
    if (t == 255) g_bsum[b] = sh[255];
}

__global__ void scan2_kernel() {
    __shared__ int sh[128];
    int t = threadIdx.x;
    int v = (t < NCHUNK) ? g_bsum[t] : 0;
    sh[t] = v;
    __syncthreads();
    for (int o = 1; o < 128; o <<= 1) {
        int x = (t >= o) ? sh[t - o] : 0;
        __syncthreads();
        sh[t] += x;
        __syncthreads();
    }
    if (t < NCHUNK) g_bsum[t] = sh[t] - v;   // exclusive
    if (t == 127)   g_off[N_NODES] = sh[127];
}

__global__ void scan3_kernel() {
    int b = blockIdx.x;
    int add = g_bsum[b];
    int base = b * 1024 + threadIdx.x * 4;
#pragma unroll
    for (int i = 0; i < 4; i++)
        if (base + i < N_NODES) g_off[base + i] += add;
}

// dinv from counts; reset counts (scatter cursors); zero pool accumulator
__global__ void dinv_reset_kernel() {
    int v = blockIdx.x * 256 + threadIdx.x;
    if (v < N_NODES) {
        g_dinv[v] = rsqrtf((float)g_count[v] + 1.0f);
        g_count[v] = 0;
    }
    if (v < HID) g_pool[v] = 0.f;
}

__global__ void scatter_kernel(const int* __restrict__ row, const int* __restrict__ col) {
    int e = blockIdx.x * 256 + threadIdx.x;
    if (e < E_EDGES) {
        int c = col[e];
        int pos = g_off[c] + atomicAdd(&g_count[c], 1);
        g_src[pos] = row[e];
    }
}

// ---------------- GEMM: Hs[n] = [dinv[n] *] (X[n] @ W), bf16 output ---------
// packed f32x2 FFMA (2x fp32 MAC throughput; ptxas never emits this itself)
template <int K, bool SCALE>
__global__ void __launch_bounds__(128)
gemm_kernel(const float* __restrict__ X, const float* __restrict__ W,
            __nv_bfloat162* __restrict__ Hs) {
    __shared__ float Ws[K * HID];
    for (int i = threadIdx.x; i < K * HID; i += 128) Ws[i] = W[i];
    __syncthreads();
    int n = blockIdx.x * 128 + threadIdx.x;
    if (n >= N_NODES) return;

    unsigned long long acc[32];
#pragma unroll
    for (int j = 0; j < 32; j++) acc[j] = 0ull;   // {+0.f, +0.f}

    const float4* xr = reinterpret_cast<const float4*>(X + (size_t)n * K);
#pragma unroll 1
    for (int k4 = 0; k4 < K / 4; k4++) {
        float4 xv = xr[k4];
        float xs[4] = {xv.x, xv.y, xv.z, xv.w};
#pragma unroll
        for (int kk = 0; kk < 4; kk++) {
            unsigned long long xx;
            asm("mov.b64 %0, {%1, %1};" : "=l"(xx) : "f"(xs[kk]));
            const ulonglong2* wr =
                reinterpret_cast<const ulonglong2*>(&Ws[(k4 * 4 + kk) * HID]);
#pragma unroll
            for (int j = 0; j < 16; j++) {
                ulonglong2 w = wr[j];
                asm("fma.rn.f32x2 %0, %1, %2, %0;" : "+l"(acc[2 * j])     : "l"(xx), "l"(w.x));
                asm("fma.rn.f32x2 %0, %1, %2, %0;" : "+l"(acc[2 * j + 1]) : "l"(xx), "l"(w.y));
            }
        }
    }
    float dv = SCALE ? g_dinv[n] : 1.0f;
    unsigned int out32[32];
#pragma unroll
    for (int j = 0; j < 32; j++) {
        float2 f = *reinterpret_cast<float2*>(&acc[j]);
        __nv_bfloat162 b = __float22bfloat162_rn(make_float2(f.x * dv, f.y * dv));
        out32[j] = *reinterpret_cast<unsigned int*>(&b);
    }
    uint4* o = reinterpret_cast<uint4*>(Hs + (size_t)n * 32);
#pragma unroll
    for (int j = 0; j < 8; j++)
        o[j] = make_uint4(out32[4 * j], out32[4 * j + 1], out32[4 * j + 2], out32[4 * j + 3]);
}

// multiply bf16 rows by dinv[v] (applied after gemm1, which runs before dinv exists)
__global__ void __launch_bounds__(256)
scale_kernel(__nv_bfloat162* __restrict__ Hs) {
    int idx = blockIdx.x * 256 + threadIdx.x;
    int v = idx >> 5;
    if (v >= N_NODES) return;
    float dv = g_dinv[v];
    float2 f = __bfloat1622float2(Hs[idx]);
    Hs[idx] = __float22bfloat162_rn(make_float2(f.x * dv, f.y * dv));
}

// ------- fused: CSR gather-aggregate + self-loop + bias + LN + ReLU ---------
// one warp per node; lane l owns features 2l, 2l+1 (bf16x2 read, fp32 math)
__global__ void __launch_bounds__(256)
agg_ln_kernel(const __nv_bfloat162* __restrict__ H2, const float* __restrict__ bias,
              const float* __restrict__ lnw, const float* __restrict__ lnb,
              float* __restrict__ Xo) {
    int v = (blockIdx.x * 256 + threadIdx.x) >> 5;
    int lane = threadIdx.x & 31;
    if (v >= N_NODES) return;

    int beg = g_off[v], end = g_off[v + 1];

    float ax = 0.f, ay = 0.f;
    int e = beg;
    for (; e + 4 <= end; e += 4) {
        int s0 = g_src[e], s1 = g_src[e + 1], s2 = g_src[e + 2], s3 = g_src[e + 3];
        float2 h0 = __bfloat1622float2(H2[(size_t)s0 * 32 + lane]);
        float2 h1 = __bfloat1622float2(H2[(size_t)s1 * 32 + lane]);
        float2 h2 = __bfloat1622float2(H2[(size_t)s2 * 32 + lane]);
        float2 h3 = __bfloat1622float2(H2[(size_t)s3 * 32 + lane]);
        ax += (h0.x + h1.x) + (h2.x + h3.x);
        ay += (h0.y + h1.y) + (h2.y + h3.y);
    }
    for (; e < end; e++) {
        int s = g_src[e];
        float2 h = __bfloat1622float2(H2[(size_t)s * 32 + lane]);
        ax += h.x; ay += h.y;
    }

    float dv = g_dinv[v];
    float2 hs = __bfloat1622float2(H2[(size_t)v * 32 + lane]);
    // Hs already carries dinv[src]; total = dv*(sum_neighbors + self)
    ax = (ax + hs.x) * dv + bias[lane * 2 + 0];
    ay = (ay + hs.y) * dv + bias[lane * 2 + 1];

    // LayerNorm over 64 features (warp reduce)
    float sum = ax + ay;
    float sq  = ax * ax + ay * ay;
#pragma unroll
    for (int o = 16; o > 0; o >>= 1) {
        sum += __shfl_xor_sync(0xffffffffu, sum, o);
        sq  += __shfl_xor_sync(0xffffffffu, sq,  o);
    }
    float mu  = sum * (1.f / 64.f);
    float var = sq * (1.f / 64.f) - mu * mu;
    float r   = rsqrtf(var + 1e-5f);
    float y0 = (ax - mu) * r * lnw[lane * 2 + 0] + lnb[lane * 2 + 0];
    float y1 = (ay - mu) * r * lnw[lane * 2 + 1] + lnb[lane * 2 + 1];
    float2 o2;
    o2.x = fmaxf(y0, 0.f);
    o2.y = fmaxf(y1, 0.f);
    reinterpret_cast<float2*>(Xo)[(size_t)v * 32 + lane] = o2;
}

// ---------------- pooling + linear head -------------------------------------
__global__ void pool_kernel(const float* __restrict__ X) {
    __shared__ float sh[256];
    int j = threadIdx.x & 63;
    int g = threadIdx.x >> 6;
    float s = 0.f;
    for (int v = blockIdx.x * 4 + g; v < N_NODES; v += gridDim.x * 4)
        s += X[(size_t)v * 64 + j];
    sh[threadIdx.x] = s;
    __syncthreads();
    if (threadIdx.x < 64)
        atomicAdd(&g_pool[j], sh[threadIdx.x] + sh[threadIdx.x + 64] +
                               sh[threadIdx.x + 128] + sh[threadIdx.x + 192]);
}

__global__ void final_kernel(const float* __restrict__ Wl, const float* __restrict__ bl,
                             float* __restrict__ out) {
    int o = threadIdx.x;
    if (o < OUT_F) {
        float s = 0.f;
#pragma unroll
        for (int j = 0; j < HID; j++) s += g_pool[j] * Wl[j * OUT_F + o];
        out[o] = s * (1.0f / N_NODES) + bl[o];
    }
}

// ---------------- launch ----------------------------------------------------
extern "C" void kernel_launch(void* const* d_in, const int* in_sizes, int n_in,
                              void* d_out, int out_size) {
    const float* x    = (const float*)d_in[0];
    const int*   ei   = (const int*)  d_in[1];
    const float* W1   = (const float*)d_in[2];
    const float* b1   = (const float*)d_in[3];
    const float* W2   = (const float*)d_in[4];
    const float* b2   = (const float*)d_in[5];
    const float* W3   = (const float*)d_in[6];
    const float* b3   = (const float*)d_in[7];
    const float* ln1w = (const float*)d_in[8];
    const float* ln1b = (const float*)d_in[9];
    const float* ln2w = (const float*)d_in[10];
    const float* ln2b = (const float*)d_in[11];
    const float* ln3w = (const float*)d_in[12];
    const float* ln3b = (const float*)d_in[13];
    const float* Wl   = (const float*)d_in[14];
    const float* bl   = (const float*)d_in[15];
    float* out = (float*)d_out;

    const int* row = ei;            // edge_index[0]
    const int* col = ei + E_EDGES;  // edge_index[1]

    __nv_bfloat162* gh = nullptr; cudaGetSymbolAddress((void**)&gh, g_h);
    float*          gx = nullptr; cudaGetSymbolAddress((void**)&gx, g_x);
    int*            gc = nullptr; cudaGetSymbolAddress((void**)&gc, g_count);

    int nB  = (N_NODES + 255) / 256;        // 391
    int eB  = (E_EDGES + 255) / 256;        // 6250
    int gB1 = (N_NODES + 127) / 128;        // 782
    int aB  = (N_NODES * 32 + 255) / 256;   // 12500 (warp/node)

    // fork a side stream for gemm1 (independent of the CSR build)
    cudaStream_t s;
    cudaStreamCreateWithFlags(&s, cudaStreamNonBlocking);
    cudaEvent_t eFork, eDinv, eJoin;
    cudaEventCreateWithFlags(&eFork, cudaEventDisableTiming);
    cudaEventCreateWithFlags(&eDinv, cudaEventDisableTiming);
    cudaEventCreateWithFlags(&eJoin, cudaEventDisableTiming);

    // ---- main stream: CSR build ----
    cudaMemsetAsync(gc, 0, N_NODES * sizeof(int), 0);
    cudaEventRecord(eFork, 0);
    count_kernel<<<eB, 256>>>(col);
    scan1_kernel<<<NCHUNK, 256>>>();
    scan2_kernel<<<1, 128>>>();
    scan3_kernel<<<NCHUNK, 256>>>();
    dinv_reset_kernel<<<nB, 256>>>();
    cudaEventRecord(eDinv, 0);
    scatter_kernel<<<eB, 256>>>(row, col);

    // ---- side stream: gemm1 (no dinv), then dinv scale once dinv is ready --
    cudaStreamWaitEvent(s, eFork, 0);
    gemm_kernel<IN_C, false><<<gB1, 128, 0, s>>>(x, W1, gh);
    cudaStreamWaitEvent(s, eDinv, 0);
    scale_kernel<<<aB, 256, 0, s>>>(gh);
    cudaEventRecord(eJoin, s);
    cudaStreamWaitEvent(0, eJoin, 0);

    // ---- join: layers sequential from here ----
    agg_ln_kernel<<<aB, 256>>>(gh, b1, ln1w, ln1b, gx);
    gemm_kernel<HID, true><<<gB1, 128>>>(gx, W2, gh);
    agg_ln_kernel<<<aB, 256>>>(gh, b2, ln2w, ln2b, gx);
    gemm_kernel<HID, true><<<gB1, 128>>>(gx, W3, gh);
    agg_ln_kernel<<<aB, 256>>>(gh, b3, ln3w, ln3b, gx);

    pool_kernel<<<512, 256>>>(gx);
    final_kernel<<<1, 32>>>(Wl, bl, out);

    cudaStreamDestroy(s);   // safe: all work joined back to stream 0
    cudaEventDestroy(eFork);
    cudaEventDestroy(eDinv);
    cudaEventDestroy(eJoin);
}

// round 5
// speedup vs baseline: 1.7791x; 1.0369x over previous
#include <cuda_runtime.h>
#include <cuda_bf16.h>

#define N_NODES 100000
#define E_EDGES 1600000
#define HID     64
#define IN_C    128
#define OUT_F   25
#define NCHUNK  98   // ceil(N/1024)

// ---------------- device scratch (static: no allocations allowed) ----------
// count/state/pool adjacent -> one memsetAsync clears all three
struct Scratch {
    int   count[N_NODES];                 // degree counts, later scatter cursor
    unsigned long long state[NCHUNK];     // decoupled-lookback scan state
    float pool[HID];                      // pooled accumulator
};
__device__ Scratch g_s;
__device__ float g_dinv [N_NODES];      // rsqrt(deg+1)
__device__ int   g_off  [N_NODES + 1];  // CSR offsets (by col)
__device__ int   g_src  [E_EDGES];      // row indices sorted by col
__device__ float g_h    [N_NODES * HID]; // Hs bf16 (reinterpreted), dinv-scaled
__device__ float g_x    [N_NODES * HID]; // fp32 activations between layers

#define FLAG_AGG  (1ull << 62)
#define FLAG_PREF (2ull << 62)

// ---------------- CSR build --------------------------------------------------
__global__ void count_kernel(const int4* __restrict__ col4) {
    int i = blockIdx.x * 256 + threadIdx.x;
    if (i < E_EDGES / 4) {
        int4 c = col4[i];
        atomicAdd(&g_s.count[c.x], 1);
        atomicAdd(&g_s.count[c.y], 1);
        atomicAdd(&g_s.count[c.z], 1);
        atomicAdd(&g_s.count[c.w], 1);
    }
}

// single-pass exclusive scan (decoupled lookback) + dinv + cursor reset
__global__ void __launch_bounds__(256)
scan_fused_kernel() {
    __shared__ int sh[256];
    __shared__ int s_prefix;
    int b = blockIdx.x, t = threadIdx.x;
    int base = b * 1024 + t * 4;
    int v0 = (base + 0 < N_NODES) ? g_s.count[base + 0] : 0;
    int v1 = (base + 1 < N_NODES) ? g_s.count[base + 1] : 0;
    int v2 = (base + 2 < N_NODES) ? g_s.count[base + 2] : 0;
    int v3 = (base + 3 < N_NODES) ? g_s.count[base + 3] : 0;
    int tot = v0 + v1 + v2 + v3;
    sh[t] = tot;
    __syncthreads();
    for (int o = 1; o < 256; o <<= 1) {
        int x = (t >= o) ? sh[t - o] : 0;
        __syncthreads();
        sh[t] += x;
        __syncthreads();
    }
    int btot = sh[255];

    if (t == 0) {
        if (b == 0) {
            s_prefix = 0;
            atomicExch(&g_s.state[0], FLAG_PREF | (unsigned long long)(unsigned)btot);
        } else {
            atomicExch(&g_s.state[b], FLAG_AGG | (unsigned long long)(unsigned)btot);
        }
    }
    // warp 0 lookback (all 98 blocks co-resident on 148 SMs -> no deadlock)
    if (b > 0 && t < 32) {
        int excl = 0;
        int hi = b - 1;
        for (;;) {
            int idx = hi - 31 + t;
            unsigned long long s;
            unsigned flag;
            for (;;) {
                s = (idx >= 0)
                    ? *((volatile unsigned long long*)&g_s.state[idx])
                    : FLAG_PREF;                 // virtual prefix 0 below idx 0
                flag = (unsigned)(s >> 62);
                if (__all_sync(0xffffffffu, flag != 0)) break;
            }
            unsigned pm = __ballot_sync(0xffffffffu, flag == 2u);
            int val = (int)(s & 0xffffffffull);
            if (pm) {
                int lp = 31 - __clz(pm);         // highest lane holding a prefix
                int contrib = (t >= lp) ? val : 0;
#pragma unroll
                for (int o = 16; o > 0; o >>= 1)
                    contrib += __shfl_xor_sync(0xffffffffu, contrib, o);
                excl += contrib;
                break;
            } else {
                int contrib = val;
#pragma unroll
                for (int o = 16; o > 0; o >>= 1)
                    contrib += __shfl_xor_sync(0xffffffffu, contrib, o);
                excl += contrib;
                hi -= 32;
            }
        }
        if (t == 0) {
            s_prefix = excl;
            atomicExch(&g_s.state[b],
                       FLAG_PREF | (unsigned long long)(unsigned)(excl + btot));
        }
    }
    __syncthreads();
    int pref = s_prefix;
    int excl = pref + sh[t] - tot;
    if (base + 0 < N_NODES) {
        g_off[base + 0] = excl;
        g_dinv[base + 0] = rsqrtf((float)v0 + 1.0f);
        g_s.count[base + 0] = 0;
    }
    if (base + 1 < N_NODES) {
        g_off[base + 1] = excl + v0;
        g_dinv[base + 1] = rsqrtf((float)v1 + 1.0f);
        g_s.count[base + 1] = 0;
    }
    if (base + 2 < N_NODES) {
        g_off[base + 2] = excl + v0 + v1;
        g_dinv[base + 2] = rsqrtf((float)v2 + 1.0f);
        g_s.count[base + 2] = 0;
    }
    if (base + 3 < N_NODES) {
        g_off[base + 3] = excl + v0 + v1 + v2;
        g_dinv[base + 3] = rsqrtf((float)v3 + 1.0f);
        g_s.count[base + 3] = 0;
    }
    if (b == NCHUNK - 1 && t == 255) g_off[N_NODES] = pref + btot;
}

__global__ void scatter_kernel(const int4* __restrict__ row4, const int4* __restrict__ col4) {
    int i = blockIdx.x * 256 + threadIdx.x;
    if (i < E_EDGES / 4) {
        int4 r = row4[i];
        int4 c = col4[i];
        g_src[g_off[c.x] + atomicAdd(&g_s.count[c.x], 1)] = r.x;
        g_src[g_off[c.y] + atomicAdd(&g_s.count[c.y], 1)] = r.y;
        g_src[g_off[c.z] + atomicAdd(&g_s.count[c.z], 1)] = r.z;
        g_src[g_off[c.w] + atomicAdd(&g_s.count[c.w], 1)] = r.w;
    }
}

// ---------------- GEMM: Hs[n] = [dinv[n] *] (X[n] @ W), bf16 output ---------
// packed f32x2 FFMA (2x fp32 MAC throughput; ptxas never emits this itself)
template <int K, bool SCALE>
__global__ void __launch_bounds__(128)
gemm_kernel(const float* __restrict__ X, const float* __restrict__ W,
            __nv_bfloat162* __restrict__ Hs) {
    __shared__ float Ws[K * HID];
    for (int i = threadIdx.x; i < K * HID; i += 128) Ws[i] = W[i];
    __syncthreads();
    int n = blockIdx.x * 128 + threadIdx.x;
    if (n >= N_NODES) return;

    unsigned long long acc[32];
#pragma unroll
    for (int j = 0; j < 32; j++) acc[j] = 0ull;   // {+0.f, +0.f}

    const float4* xr = reinterpret_cast<const float4*>(X + (size_t)n * K);
#pragma unroll 1
    for (int k4 = 0; k4 < K / 4; k4++) {
        float4 xv = xr[k4];
        float xs[4] = {xv.x, xv.y, xv.z, xv.w};
#pragma unroll
        for (int kk = 0; kk < 4; kk++) {
            unsigned long long xx;
            asm("mov.b64 %0, {%1, %1};" : "=l"(xx) : "f"(xs[kk]));
            const ulonglong2* wr =
                reinterpret_cast<const ulonglong2*>(&Ws[(k4 * 4 + kk) * HID]);
#pragma unroll
            for (int j = 0; j < 16; j++) {
                ulonglong2 w = wr[j];
                asm("fma.rn.f32x2 %0, %1, %2, %0;" : "+l"(acc[2 * j])     : "l"(xx), "l"(w.x));
                asm("fma.rn.f32x2 %0, %1, %2, %0;" : "+l"(acc[2 * j + 1]) : "l"(xx), "l"(w.y));
            }
        }
    }
    float dv = SCALE ? g_dinv[n] : 1.0f;
    unsigned int out32[32];
#pragma unroll
    for (int j = 0; j < 32; j++) {
        float2 f = *reinterpret_cast<float2*>(&acc[j]);
        __nv_bfloat162 b = __float22bfloat162_rn(make_float2(f.x * dv, f.y * dv));
        out32[j] = *reinterpret_cast<unsigned int*>(&b);
    }
    uint4* o = reinterpret_cast<uint4*>(Hs + (size_t)n * 32);
#pragma unroll
    for (int j = 0; j < 8; j++)
        o[j] = make_uint4(out32[4 * j], out32[4 * j + 1], out32[4 * j + 2], out32[4 * j + 3]);
}

// multiply bf16 rows by dinv[v] (applied after gemm1, which runs before dinv exists)
__global__ void __launch_bounds__(256)
scale_kernel(__nv_bfloat162* __restrict__ Hs) {
    int idx = blockIdx.x * 256 + threadIdx.x;
    int v = idx >> 5;
    if (v >= N_NODES) return;
    float dv = g_dinv[v];
    float2 f = __bfloat1622float2(Hs[idx]);
    Hs[idx] = __float22bfloat162_rn(make_float2(f.x * dv, f.y * dv));
}

// ------- fused: CSR gather-aggregate + self-loop + bias + LN + ReLU ---------
// one warp per node; lane l owns features 2l, 2l+1 (bf16x2 read, fp32 math)
__device__ __forceinline__ void agg_node(
    int v, int lane, const __nv_bfloat162* __restrict__ H2,
    const float* __restrict__ bias, const float* __restrict__ lnw,
    const float* __restrict__ lnb, float& y0o, float& y1o) {
    int beg = g_off[v], end = g_off[v + 1];

    float ax = 0.f, ay = 0.f;
    int e = beg;
    for (; e + 4 <= end; e += 4) {
        int s0 = g_src[e], s1 = g_src[e + 1], s2 = g_src[e + 2], s3 = g_src[e + 3];
        float2 h0 = __bfloat1622float2(H2[(size_t)s0 * 32 + lane]);
        float2 h1 = __bfloat1622float2(H2[(size_t)s1 * 32 + lane]);
        float2 h2 = __bfloat1622float2(H2[(size_t)s2 * 32 + lane]);
        float2 h3 = __bfloat1622float2(H2[(size_t)s3 * 32 + lane]);
        ax += (h0.x + h1.x) + (h2.x + h3.x);
        ay += (h0.y + h1.y) + (h2.y + h3.y);
    }
    for (; e < end; e++) {
        int s = g_src[e];
        float2 h = __bfloat1622float2(H2[(size_t)s * 32 + lane]);
        ax += h.x; ay += h.y;
    }

    float dv = g_dinv[v];
    float2 hs = __bfloat1622float2(H2[(size_t)v * 32 + lane]);
    // Hs already carries dinv[src]; total = dv*(sum_neighbors + self)
    ax = (ax + hs.x) * dv + bias[lane * 2 + 0];
    ay = (ay + hs.y) * dv + bias[lane * 2 + 1];

    // LayerNorm over 64 features (warp reduce)
    float sum = ax + ay;
    float sq  = ax * ax + ay * ay;
#pragma unroll
    for (int o = 16; o > 0; o >>= 1) {
        sum += __shfl_xor_sync(0xffffffffu, sum, o);
        sq  += __shfl_xor_sync(0xffffffffu, sq,  o);
    }
    float mu  = sum * (1.f / 64.f);
    float var = sq * (1.f / 64.f) - mu * mu;
    float r   = rsqrtf(var + 1e-5f);
    float t0 = (ax - mu) * r * lnw[lane * 2 + 0] + lnb[lane * 2 + 0];
    float t1 = (ay - mu) * r * lnw[lane * 2 + 1] + lnb[lane * 2 + 1];
    y0o = fmaxf(t0, 0.f);
    y1o = fmaxf(t1, 0.f);
}

__global__ void __launch_bounds__(256)
agg_ln_kernel(const __nv_bfloat162* __restrict__ H2, const float* __restrict__ bias,
              const float* __restrict__ lnw, const float* __restrict__ lnb,
              float* __restrict__ Xo) {
    int v = (blockIdx.x * 256 + threadIdx.x) >> 5;
    int lane = threadIdx.x & 31;
    if (v >= N_NODES) return;
    float y0, y1;
    agg_node(v, lane, H2, bias, lnw, lnb, y0, y1);
    reinterpret_cast<float2*>(Xo)[(size_t)v * 32 + lane] = make_float2(y0, y1);
}

// layer 3: never materialize activations; accumulate the mean-pool directly
#define POOL_BLOCKS 1184
__global__ void __launch_bounds__(256)
agg_ln_pool_kernel(const __nv_bfloat162* __restrict__ H2, const float* __restrict__ bias,
                   const float* __restrict__ lnw, const float* __restrict__ lnb) {
    __shared__ float shp[8 * 64];
    int w    = threadIdx.x >> 5;
    int lane = threadIdx.x & 31;
    int gw   = blockIdx.x * 8 + w;            // global warp id
    const int nw = POOL_BLOCKS * 8;

    float px = 0.f, py = 0.f;
    for (int v = gw; v < N_NODES; v += nw) {
        float y0, y1;
        agg_node(v, lane, H2, bias, lnw, lnb, y0, y1);
        px += y0; py += y1;
    }
    shp[w * 64 + lane * 2 + 0] = px;
    shp[w * 64 + lane * 2 + 1] = py;
    __syncthreads();
    if (threadIdx.x < 64) {
        float s = 0.f;
#pragma unroll
        for (int k = 0; k < 8; k++) s += shp[k * 64 + threadIdx.x];
        atomicAdd(&g_s.pool[threadIdx.x], s);
    }
}

__global__ void final_kernel(const float* __restrict__ Wl, const float* __restrict__ bl,
                             float* __restrict__ out) {
    int o = threadIdx.x;
    if (o < OUT_F) {
        float s = 0.f;
#pragma unroll
        for (int j = 0; j < HID; j++) s += g_s.pool[j] * Wl[j * OUT_F + o];
        out[o] = s * (1.0f / N_NODES) + bl[o];
    }
}

// ---------------- launch ----------------------------------------------------
extern "C" void kernel_launch(void* const* d_in, const int* in_sizes, int n_in,
                              void* d_out, int out_size) {
    const float* x    = (const float*)d_in[0];
    const int*   ei   = (const int*)  d_in[1];
    const float* W1   = (const float*)d_in[2];
    const float* b1   = (const float*)d_in[3];
    const float* W2   = (const float*)d_in[4];
    const float* b2   = (const float*)d_in[5];
    const float* W3   = (const float*)d_in[6];
    const float* b3   = (const float*)d_in[7];
    const float* ln1w = (const float*)d_in[8];
    const float* ln1b = (const float*)d_in[9];
    const float* ln2w = (const float*)d_in[10];
    const float* ln2b = (const float*)d_in[11];
    const float* ln3w = (const float*)d_in[12];
    const float* ln3b = (const float*)d_in[13];
    const float* Wl   = (const float*)d_in[14];
    const float* bl   = (const float*)d_in[15];
    float* out = (float*)d_out;

    const int4* row4 = (const int4*)(ei);             // edge_index[0]
    const int4* col4 = (const int4*)(ei + E_EDGES);   // edge_index[1]

    __nv_bfloat162* gh = nullptr; cudaGetSymbolAddress((void**)&gh, g_h);
    float*          gx = nullptr; cudaGetSymbolAddress((void**)&gx, g_x);
    void*           gs = nullptr; cudaGetSymbolAddress(&gs, g_s);

    int eB4 = (E_EDGES / 4 + 255) / 256;    // 1563
    int gB1 = (N_NODES + 127) / 128;        // 782
    int aB  = (N_NODES * 32 + 255) / 256;   // 12500 (warp/node)

    // fork a side stream for gemm1 (independent of the CSR build)
    cudaStream_t s;
    cudaStreamCreateWithFlags(&s, cudaStreamNonBlocking);
    cudaEvent_t eFork, eDinv, eJoin;
    cudaEventCreateWithFlags(&eFork, cudaEventDisableTiming);
    cudaEventCreateWithFlags(&eDinv, cudaEventDisableTiming);
    cudaEventCreateWithFlags(&eJoin, cudaEventDisableTiming);

    // ---- main stream: CSR build ----
    cudaMemsetAsync(gs, 0, sizeof(Scratch), 0);   // count + scan state + pool
    cudaEventRecord(eFork, 0);
    count_kernel<<<eB4, 256>>>(col4);
    scan_fused_kernel<<<NCHUNK, 256>>>();
    cudaEventRecord(eDinv, 0);
    scatter_kernel<<<eB4, 256>>>(row4, col4);

    // ---- side stream: gemm1 (no dinv), then dinv scale once dinv is ready --
    cudaStreamWaitEvent(s, eFork, 0);
    gemm_kernel<IN_C, false><<<gB1, 128, 0, s>>>(x, W1, gh);
    cudaStreamWaitEvent(s, eDinv, 0);
    scale_kernel<<<aB, 256, 0, s>>>(gh);
    cudaEventRecord(eJoin, s);
    cudaStreamWaitEvent(0, eJoin, 0);

    // ---- join: layers sequential from here ----
    agg_ln_kernel<<<aB, 256>>>(gh, b1, ln1w, ln1b, gx);
    gemm_kernel<HID, true><<<gB1, 128>>>(gx, W2, gh);
    agg_ln_kernel<<<aB, 256>>>(gh, b2, ln2w, ln2b, gx);
    gemm_kernel<HID, true><<<gB1, 128>>>(gx, W3, gh);
    agg_ln_pool_kernel<<<POOL_BLOCKS, 256>>>(gh, b3, ln3w, ln3b);
    final_kernel<<<1, 32>>>(Wl, bl, out);

    cudaStreamDestroy(s);   // safe: all work joined back to stream 0
    cudaEventDestroy(eFork);
    cudaEventDestroy(eDinv);
    cudaEventDestroy(eJoin);
}

// round 7
// speedup vs baseline: 2.2093x; 1.2418x over previous
#include <cuda_runtime.h>
#include <cuda_bf16.h>

#define N_NODES 100000
#define E_EDGES 1600000
#define HID     64
#define IN_C    128
#define OUT_F   25
#define NCHUNK  98   // ceil(N/1024)

// ---------------- device scratch (static: no allocations allowed) ----------
// count/state/pool adjacent -> one memsetAsync clears all three
struct Scratch {
    int   count[N_NODES];                 // degree counts, later scatter cursor
    unsigned long long state[NCHUNK];     // decoupled-lookback scan state
    float pool[HID];                      // pooled accumulator
};
__device__ Scratch g_s;
__device__ float g_dinv [N_NODES];      // rsqrt(deg+1)
__device__ int   g_off  [N_NODES + 1];  // CSR offsets (by col)
__device__ int   g_src  [E_EDGES];      // row indices sorted by col
__device__ float g_h    [N_NODES * HID]; // Hs bf16 (reinterpreted), dinv-scaled
__device__ float g_x    [N_NODES * HID]; // fp32 activations between layers

#define FLAG_AGG  (1ull << 62)
#define FLAG_PREF (2ull << 62)

// ---------------- CSR build --------------------------------------------------
__global__ void count_kernel(const int4* __restrict__ col4) {
    int i = blockIdx.x * 256 + threadIdx.x;
    if (i < E_EDGES / 4) {
        int4 c = col4[i];
        atomicAdd(&g_s.count[c.x], 1);
        atomicAdd(&g_s.count[c.y], 1);
        atomicAdd(&g_s.count[c.z], 1);
        atomicAdd(&g_s.count[c.w], 1);
    }
}

// single-pass exclusive scan (decoupled lookback) + dinv + cursor reset
__global__ void __launch_bounds__(256)
scan_fused_kernel() {
    __shared__ int sh[256];
    __shared__ int s_prefix;
    int b = blockIdx.x, t = threadIdx.x;
    int base = b * 1024 + t * 4;
    int v0 = (base + 0 < N_NODES) ? g_s.count[base + 0] : 0;
    int v1 = (base + 1 < N_NODES) ? g_s.count[base + 1] : 0;
    int v2 = (base + 2 < N_NODES) ? g_s.count[base + 2] : 0;
    int v3 = (base + 3 < N_NODES) ? g_s.count[base + 3] : 0;
    int tot = v0 + v1 + v2 + v3;
    sh[t] = tot;
    __syncthreads();
    for (int o = 1; o < 256; o <<= 1) {
        int x = (t >= o) ? sh[t - o] : 0;
        __syncthreads();
        sh[t] += x;
        __syncthreads();
    }
    int btot = sh[255];

    if (t == 0) {
        if (b == 0) {
            s_prefix = 0;
            atomicExch(&g_s.state[0], FLAG_PREF | (unsigned long long)(unsigned)btot);
        } else {
            atomicExch(&g_s.state[b], FLAG_AGG | (unsigned long long)(unsigned)btot);
        }
    }
    // warp 0 lookback (all 98 blocks co-resident on 148 SMs -> no deadlock)
    if (b > 0 && t < 32) {
        int excl = 0;
        int hi = b - 1;
        for (;;) {
            int idx = hi - 31 + t;
            unsigned long long s;
            unsigned flag;
            for (;;) {
                s = (idx >= 0)
                    ? *((volatile unsigned long long*)&g_s.state[idx])
                    : FLAG_PREF;                 // virtual prefix 0 below idx 0
                flag = (unsigned)(s >> 62);
                if (__all_sync(0xffffffffu, flag != 0)) break;
            }
            unsigned pm = __ballot_sync(0xffffffffu, flag == 2u);
            int val = (int)(s & 0xffffffffull);
            if (pm) {
                int lp = 31 - __clz(pm);         // highest lane holding a prefix
                int contrib = (t >= lp) ? val : 0;
#pragma unroll
                for (int o = 16; o > 0; o >>= 1)
                    contrib += __shfl_xor_sync(0xffffffffu, contrib, o);
                excl += contrib;
                break;
            } else {
                int contrib = val;
#pragma unroll
                for (int o = 16; o > 0; o >>= 1)
                    contrib += __shfl_xor_sync(0xffffffffu, contrib, o);
                excl += contrib;
                hi -= 32;
            }
        }
        if (t == 0) {
            s_prefix = excl;
            atomicExch(&g_s.state[b],
                       FLAG_PREF | (unsigned long long)(unsigned)(excl + btot));
        }
    }
    __syncthreads();
    int pref = s_prefix;
    int excl = pref + sh[t] - tot;
    if (base + 0 < N_NODES) {
        g_off[base + 0] = excl;
        g_dinv[base + 0] = rsqrtf((float)v0 + 1.0f);
        g_s.count[base + 0] = 0;
    }
    if (base + 1 < N_NODES) {
        g_off[base + 1] = excl + v0;
        g_dinv[base + 1] = rsqrtf((float)v1 + 1.0f);
        g_s.count[base + 1] = 0;
    }
    if (base + 2 < N_NODES) {
        g_off[base + 2] = excl + v0 + v1;
        g_dinv[base + 2] = rsqrtf((float)v2 + 1.0f);
        g_s.count[base + 2] = 0;
    }
    if (base + 3 < N_NODES) {
        g_off[base + 3] = excl + v0 + v1 + v2;
        g_dinv[base + 3] = rsqrtf((float)v3 + 1.0f);
        g_s.count[base + 3] = 0;
    }
    if (b == NCHUNK - 1 && t == 255) g_off[N_NODES] = pref + btot;
}

__global__ void scatter_kernel(const int4* __restrict__ row4, const int4* __restrict__ col4) {
    int i = blockIdx.x * 256 + threadIdx.x;
    if (i < E_EDGES / 4) {
        int4 r = row4[i];
        int4 c = col4[i];
        g_src[g_off[c.x] + atomicAdd(&g_s.count[c.x], 1)] = r.x;
        g_src[g_off[c.y] + atomicAdd(&g_s.count[c.y], 1)] = r.y;
        g_src[g_off[c.z] + atomicAdd(&g_s.count[c.z], 1)] = r.z;
        g_src[g_off[c.w] + atomicAdd(&g_s.count[c.w], 1)] = r.w;
    }
}

// ---------------- GEMM: Hs[n] = [dinv[n] *] (X[n] @ W), bf16 output ---------
// 2D register tiling: block = 64 nodes x 64 feats, thread = 4 nodes x 8 feats.
// Per k: 3 LDS.128 for 16 FFMA2 (packed f32x2 MACs).
template <int K, bool SCALE>
__global__ void __launch_bounds__(128)
gemm_kernel(const float* __restrict__ X, const float* __restrict__ W,
            __nv_bfloat162* __restrict__ Hs) {
    __shared__ float Xs[32][68];   // [k][node], padded (bank spread + 16B align)
    __shared__ float Ws[32][64];   // [k][j]
    int tid = threadIdx.x;
    int tx = tid & 15;             // node group: nodes m0 + tx*4 .. +3
    int ty = tid >> 4;             // feat group: j = ty*8 .. +7
    int m0 = blockIdx.x * 64;

    unsigned long long acc[4][4];  // [mi][j-pair] f32x2
#pragma unroll
    for (int a = 0; a < 4; a++)
#pragma unroll
        for (int b = 0; b < 4; b++) acc[a][b] = 0ull;

    for (int kc = 0; kc < K; kc += 32) {
        // stage X chunk transposed: Xs[k][node]
#pragma unroll
        for (int l = 0; l < 4; l++) {
            int idx  = l * 128 + tid;
            int node = idx >> 3;          // 0..63
            int kq   = idx & 7;           // 0..7  (float4 along k)
            int m = m0 + node;
            float4 v = make_float4(0.f, 0.f, 0.f, 0.f);
            if (m < N_NODES)
                v = *reinterpret_cast<const float4*>(&X[(size_t)m * K + kc + kq * 4]);
            Xs[kq * 4 + 0][node] = v.x;
            Xs[kq * 4 + 1][node] = v.y;
            Xs[kq * 4 + 2][node] = v.z;
            Xs[kq * 4 + 3][node] = v.w;
        }
        // stage W chunk: Ws[k][j]
#pragma unroll
        for (int l = 0; l < 4; l++) {
            int idx = l * 128 + tid;
            int k  = idx >> 4;            // 0..31
            int jq = idx & 15;            // 0..15 (float4 along j)
            *reinterpret_cast<float4*>(&Ws[k][jq * 4]) =
                *reinterpret_cast<const float4*>(&W[(size_t)(kc + k) * HID + jq * 4]);
        }
        __syncthreads();

#pragma unroll
        for (int k = 0; k < 32; k++) {
            float4 xv = *reinterpret_cast<const float4*>(&Xs[k][tx * 4]);
            ulonglong2 wa = *reinterpret_cast<const ulonglong2*>(&Ws[k][ty * 8]);
            ulonglong2 wb = *reinterpret_cast<const ulonglong2*>(&Ws[k][ty * 8 + 4]);
            float xs[4] = {xv.x, xv.y, xv.z, xv.w};
#pragma unroll
            for (int mi = 0; mi < 4; mi++) {
                unsigned long long xx;
                asm("mov.b64 %0, {%1, %1};" : "=l"(xx) : "f"(xs[mi]));
                asm("fma.rn.f32x2 %0, %1, %2, %0;" : "+l"(acc[mi][0]) : "l"(xx), "l"(wa.x));
                asm("fma.rn.f32x2 %0, %1, %2, %0;" : "+l"(acc[mi][1]) : "l"(xx), "l"(wa.y));
                asm("fma.rn.f32x2 %0, %1, %2, %0;" : "+l"(acc[mi][2]) : "l"(xx), "l"(wb.x));
                asm("fma.rn.f32x2 %0, %1, %2, %0;" : "+l"(acc[mi][3]) : "l"(xx), "l"(wb.y));
            }
        }
        __syncthreads();
    }

#pragma unroll
    for (int mi = 0; mi < 4; mi++) {
        int m = m0 + tx * 4 + mi;
        if (m < N_NODES) {
            float dv = SCALE ? g_dinv[m] : 1.0f;
            unsigned int o[4];
#pragma unroll
            for (int jp = 0; jp < 4; jp++) {
                float2 f = *reinterpret_cast<float2*>(&acc[mi][jp]);
                __nv_bfloat162 b = __float22bfloat162_rn(make_float2(f.x * dv, f.y * dv));
                o[jp] = *reinterpret_cast<unsigned int*>(&b);
            }
            *reinterpret_cast<uint4*>(&Hs[(size_t)m * 32 + ty * 4]) =
                make_uint4(o[0], o[1], o[2], o[3]);
        }
    }
}

// multiply bf16 rows by dinv[v] (applied after gemm1, which runs before dinv exists)
__global__ void __launch_bounds__(256)
scale_kernel(__nv_bfloat162* __restrict__ Hs) {
    int idx = blockIdx.x * 256 + threadIdx.x;
    int v = idx >> 5;
    if (v >= N_NODES) return;
    float dv = g_dinv[v];
    float2 f = __bfloat1622float2(Hs[idx]);
    Hs[idx] = __float22bfloat162_rn(make_float2(f.x * dv, f.y * dv));
}

// ------- fused: CSR gather-aggregate + self-loop + bias + LN + ReLU ---------
// one warp per node; lane l owns features 2l, 2l+1 (bf16x2 read, fp32 math)
__device__ __forceinline__ void agg_node(
    int v, int lane, const __nv_bfloat162* __restrict__ H2,
    const float* __restrict__ bias, const float* __restrict__ lnw,
    const float* __restrict__ lnb, float& y0o, float& y1o) {
    int beg = g_off[v], end = g_off[v + 1];

    float ax = 0.f, ay = 0.f;
    int e = beg;
    for (; e + 4 <= end; e += 4) {
        int s0 = g_src[e], s1 = g_src[e + 1], s2 = g_src[e + 2], s3 = g_src[e + 3];
        float2 h0 = __bfloat1622float2(H2[(size_t)s0 * 32 + lane]);
        float2 h1 = __bfloat1622float2(H2[(size_t)s1 * 32 + lane]);
        float2 h2 = __bfloat1622float2(H2[(size_t)s2 * 32 + lane]);
        float2 h3 = __bfloat1622float2(H2[(size_t)s3 * 32 + lane]);
        ax += (h0.x + h1.x) + (h2.x + h3.x);
        ay += (h0.y + h1.y) + (h2.y + h3.y);
    }
    for (; e < end; e++) {
        int s = g_src[e];
        float2 h = __bfloat1622float2(H2[(size_t)s * 32 + lane]);
        ax += h.x; ay += h.y;
    }

    float dv = g_dinv[v];
    float2 hs = __bfloat1622float2(H2[(size_t)v * 32 + lane]);
    // Hs already carries dinv[src]; total = dv*(sum_neighbors + self)
    ax = (ax + hs.x) * dv + bias[lane * 2 + 0];
    ay = (ay + hs.y) * dv + bias[lane * 2 + 1];

    // LayerNorm over 64 features (warp reduce)
    float sum = ax + ay;
    float sq  = ax * ax + ay * ay;
#pragma unroll
    for (int o = 16; o > 0; o >>= 1) {
        sum += __shfl_xor_sync(0xffffffffu, sum, o);
        sq  += __shfl_xor_sync(0xffffffffu, sq,  o);
    }
    float mu  = sum * (1.f / 64.f);
    float var = sq * (1.f / 64.f) - mu * mu;
    float r   = rsqrtf(var + 1e-5f);
    float t0 = (ax - mu) * r * lnw[lane * 2 + 0] + lnb[lane * 2 + 0];
    float t1 = (ay - mu) * r * lnw[lane * 2 + 1] + lnb[lane * 2 + 1];
    y0o = fmaxf(t0, 0.f);
    y1o = fmaxf(t1, 0.f);
}

__global__ void __launch_bounds__(256)
agg_ln_kernel(const __nv_bfloat162* __restrict__ H2, const float* __restrict__ bias,
              const float* __restrict__ lnw, const float* __restrict__ lnb,
              float* __restrict__ Xo) {
    int v = (blockIdx.x * 256 + threadIdx.x) >> 5;
    int lane = threadIdx.x & 31;
    if (v >= N_NODES) return;
    float y0, y1;
    agg_node(v, lane, H2, bias, lnw, lnb, y0, y1);
    reinterpret_cast<float2*>(Xo)[(size_t)v * 32 + lane] = make_float2(y0, y1);
}

// layer 3: never materialize activations; accumulate the mean-pool directly
#define POOL_BLOCKS 1184
__global__ void __launch_bounds__(256)
agg_ln_pool_kernel(const __nv_bfloat162* __restrict__ H2, const float* __restrict__ bias,
                   const float* __restrict__ lnw, const float* __restrict__ lnb) {
    __shared__ float shp[8 * 64];
    int w    = threadIdx.x >> 5;
    int lane = threadIdx.x & 31;
    int gw   = blockIdx.x * 8 + w;            // global warp id
    const int nw = POOL_BLOCKS * 8;

    float px = 0.f, py = 0.f;
    for (int v = gw; v < N_NODES; v += nw) {
        float y0, y1;
        agg_node(v, lane, H2, bias, lnw, lnb, y0, y1);
        px += y0; py += y1;
    }
    shp[w * 64 + lane * 2 + 0] = px;
    shp[w * 64 + lane * 2 + 1] = py;
    __syncthreads();
    if (threadIdx.x < 64) {
        float s = 0.f;
#pragma unroll
        for (int k = 0; k < 8; k++) s += shp[k * 64 + threadIdx.x];
        atomicAdd(&g_s.pool[threadIdx.x], s);
    }
}

__global__ void final_kernel(const float* __restrict__ Wl, const float* __restrict__ bl,
                             float* __restrict__ out) {
    int o = threadIdx.x;
    if (o < OUT_F) {
        float s = 0.f;
#pragma unroll
        for (int j = 0; j < HID; j++) s += g_s.pool[j] * Wl[j * OUT_F + o];
        out[o] = s * (1.0f / N_NODES) + bl[o];
    }
}

// ---------------- launch ----------------------------------------------------
extern "C" void kernel_launch(void* const* d_in, const int* in_sizes, int n_in,
                              void* d_out, int out_size) {
    const float* x    = (const float*)d_in[0];
    const int*   ei   = (const int*)  d_in[1];
    const float* W1   = (const float*)d_in[2];
    const float* b1   = (const float*)d_in[3];
    const float* W2   = (const float*)d_in[4];
    const float* b2   = (const float*)d_in[5];
    const float* W3   = (const float*)d_in[6];
    const float* b3   = (const float*)d_in[7];
    const float* ln1w = (const float*)d_in[8];
    const float* ln1b = (const float*)d_in[9];
    const float* ln2w = (const float*)d_in[10];
    const float* ln2b = (const float*)d_in[11];
    const float* ln3w = (const float*)d_in[12];
    const float* ln3b = (const float*)d_in[13];
    const float* Wl   = (const float*)d_in[14];
    const float* bl   = (const float*)d_in[15];
    float* out = (float*)d_out;

    const int4* row4 = (const int4*)(ei);             // edge_index[0]
    const int4* col4 = (const int4*)(ei + E_EDGES);   // edge_index[1]

    __nv_bfloat162* gh = nullptr; cudaGetSymbolAddress((void**)&gh, g_h);
    float*          gx = nullptr; cudaGetSymbolAddress((void**)&gx, g_x);
    void*           gs = nullptr; cudaGetSymbolAddress(&gs, g_s);

    int eB4 = (E_EDGES / 4 + 255) / 256;    // 1563
    int gB  = (N_NODES + 63) / 64;          // 1563 (64-node tiles)
    int aB  = (N_NODES * 32 + 255) / 256;   // 12500 (warp/node)

    // fork a side stream for gemm1 (independent of the CSR build)
    cudaStream_t s;
    cudaStreamCreateWithFlags(&s, cudaStreamNonBlocking);
    cudaEvent_t eFork, eDinv, eJoin;
    cudaEventCreateWithFlags(&eFork, cudaEventDisableTiming);
    cudaEventCreateWithFlags(&eDinv, cudaEventDisableTiming);
    cudaEventCreateWithFlags(&eJoin, cudaEventDisableTiming);

    // ---- main stream: CSR build ----
    cudaMemsetAsync(gs, 0, sizeof(Scratch), 0);   // count + scan state + pool
    cudaEventRecord(eFork, 0);
    count_kernel<<<eB4, 256>>>(col4);
    scan_fused_kernel<<<NCHUNK, 256>>>();
    cudaEventRecord(eDinv, 0);
    scatter_kernel<<<eB4, 256>>>(row4, col4);

    // ---- side stream: gemm1 (no dinv), then dinv scale once dinv is ready --
    cudaStreamWaitEvent(s, eFork, 0);
    gemm_kernel<IN_C, false><<<gB, 128, 0, s>>>(x, W1, gh);
    cudaStreamWaitEvent(s, eDinv, 0);
    scale_kernel<<<aB, 256, 0, s>>>(gh);
    cudaEventRecord(eJoin, s);
    cudaStreamWaitEvent(0, eJoin, 0);

    // ---- join: layers sequential from here ----
    agg_ln_kernel<<<aB, 256>>>(gh, b1, ln1w, ln1b, gx);
    gemm_kernel<HID, true><<<gB, 128>>>(gx, W2, gh);
    agg_ln_kernel<<<aB, 256>>>(gh, b2, ln2w, ln2b, gx);
    gemm_kernel<HID, true><<<gB, 128>>>(gx, W3, gh);
    agg_ln_pool_kernel<<<POOL_BLOCKS, 256>>>(gh, b3, ln3w, ln3b);
    final_kernel<<<1, 32>>>(Wl, bl, out);

    cudaStreamDestroy(s);   // safe: all work joined back to stream 0
    cudaEventDestroy(eFork);
    cudaEventDestroy(eDinv);
    cudaEventDestroy(eJoin);
}

// round 8
// speedup vs baseline: 2.6249x; 1.1881x over previous
#include <cuda_runtime.h>
#include <cuda_bf16.h>
#include <cstdint>

#define N_NODES 100000
#define E_EDGES 1600000
#define HID     64
#define IN_C    128
#define OUT_F   25
#define NCHUNK  98   // ceil(N/1024)
#define XP      72   // smem pitch (bf16) -> 144B row stride: conflict-free ldmatrix

// ---------------- device scratch (static: no allocations allowed) ----------
struct Scratch {
    int   count[N_NODES];                 // degree counts, later scatter cursor
    unsigned long long state[NCHUNK];     // decoupled-lookback scan state
    float pool[HID];                      // pooled accumulator
};
__device__ Scratch g_s;
__device__ float g_dinv [N_NODES];      // rsqrt(deg+1)
__device__ int   g_off  [N_NODES + 1];  // CSR offsets (by col)
__device__ int   g_src  [E_EDGES];      // row indices sorted by col
__device__ float g_h    [N_NODES * HID]; // Hs bf16 (reinterpreted), dinv-scaled
__device__ float g_x    [N_NODES * HID]; // bf16 activations between layers (reinterpreted)

#define FLAG_AGG  (1ull << 62)
#define FLAG_PREF (2ull << 62)

// ---------------- CSR build --------------------------------------------------
__global__ void count_kernel(const int4* __restrict__ col4) {
    int i = blockIdx.x * 256 + threadIdx.x;
    if (i < E_EDGES / 4) {
        int4 c = col4[i];
        atomicAdd(&g_s.count[c.x], 1);
        atomicAdd(&g_s.count[c.y], 1);
        atomicAdd(&g_s.count[c.z], 1);
        atomicAdd(&g_s.count[c.w], 1);
    }
}

// single-pass exclusive scan (decoupled lookback) + dinv + cursor reset
__global__ void __launch_bounds__(256)
scan_fused_kernel() {
    __shared__ int sh[256];
    __shared__ int s_prefix;
    int b = blockIdx.x, t = threadIdx.x;
    int base = b * 1024 + t * 4;
    int v0 = (base + 0 < N_NODES) ? g_s.count[base + 0] : 0;
    int v1 = (base + 1 < N_NODES) ? g_s.count[base + 1] : 0;
    int v2 = (base + 2 < N_NODES) ? g_s.count[base + 2] : 0;
    int v3 = (base + 3 < N_NODES) ? g_s.count[base + 3] : 0;
    int tot = v0 + v1 + v2 + v3;
    sh[t] = tot;
    __syncthreads();
    for (int o = 1; o < 256; o <<= 1) {
        int x = (t >= o) ? sh[t - o] : 0;
        __syncthreads();
        sh[t] += x;
        __syncthreads();
    }
    int btot = sh[255];

    if (t == 0) {
        if (b == 0) {
            s_prefix = 0;
            atomicExch(&g_s.state[0], FLAG_PREF | (unsigned long long)(unsigned)btot);
        } else {
            atomicExch(&g_s.state[b], FLAG_AGG | (unsigned long long)(unsigned)btot);
        }
    }
    if (b > 0 && t < 32) {
        int excl = 0;
        int hi = b - 1;
        for (;;) {
            int idx = hi - 31 + t;
            unsigned long long s;
            unsigned flag;
            for (;;) {
                s = (idx >= 0)
                    ? *((volatile unsigned long long*)&g_s.state[idx])
                    : FLAG_PREF;
                flag = (unsigned)(s >> 62);
                if (__all_sync(0xffffffffu, flag != 0)) break;
            }
            unsigned pm = __ballot_sync(0xffffffffu, flag == 2u);
            int val = (int)(s & 0xffffffffull);
            if (pm) {
                int lp = 31 - __clz(pm);
                int contrib = (t >= lp) ? val : 0;
#pragma unroll
                for (int o = 16; o > 0; o >>= 1)
                    contrib += __shfl_xor_sync(0xffffffffu, contrib, o);
                excl += contrib;
                break;
            } else {
                int contrib = val;
#pragma unroll
                for (int o = 16; o > 0; o >>= 1)
                    contrib += __shfl_xor_sync(0xffffffffu, contrib, o);
                excl += contrib;
                hi -= 32;
            }
        }
        if (t == 0) {
            s_prefix = excl;
            atomicExch(&g_s.state[b],
                       FLAG_PREF | (unsigned long long)(unsigned)(excl + btot));
        }
    }
    __syncthreads();
    int pref = s_prefix;
    int excl = pref + sh[t] - tot;
    if (base + 0 < N_NODES) {
        g_off[base + 0] = excl;
        g_dinv[base + 0] = rsqrtf((float)v0 + 1.0f);
        g_s.count[base + 0] = 0;
    }
    if (base + 1 < N_NODES) {
        g_off[base + 1] = excl + v0;
        g_dinv[base + 1] = rsqrtf((float)v1 + 1.0f);
        g_s.count[base + 1] = 0;
    }
    if (base + 2 < N_NODES) {
        g_off[base + 2] = excl + v0 + v1;
        g_dinv[base + 2] = rsqrtf((float)v2 + 1.0f);
        g_s.count[base + 2] = 0;
    }
    if (base + 3 < N_NODES) {
        g_off[base + 3] = excl + v0 + v1 + v2;
        g_dinv[base + 3] = rsqrtf((float)v3 + 1.0f);
        g_s.count[base + 3] = 0;
    }
    if (b == NCHUNK - 1 && t == 255) g_off[N_NODES] = pref + btot;
}

__global__ void scatter_kernel(const int4* __restrict__ row4, const int4* __restrict__ col4) {
    int i = blockIdx.x * 256 + threadIdx.x;
    if (i < E_EDGES / 4) {
        int4 r = row4[i];
        int4 c = col4[i];
        g_src[g_off[c.x] + atomicAdd(&g_s.count[c.x], 1)] = r.x;
        g_src[g_off[c.y] + atomicAdd(&g_s.count[c.y], 1)] = r.y;
        g_src[g_off[c.z] + atomicAdd(&g_s.count[c.z], 1)] = r.z;
        g_src[g_off[c.w] + atomicAdd(&g_s.count[c.w], 1)] = r.w;
    }
}

// ---------------- tensor-core GEMM ------------------------------------------
// Hs[n] = [dinv[n] *] (X[n] @ W), bf16 out.  mma.sync m16n8k16 bf16, fp32 acc.
// W split hi+lo (two bf16 mats) so weight rounding error is ~2^-17 (coherent-
// across-nodes error must stay tiny; activation rounding pools away).
// Block: 128 thr = 4 warps, 64-node x 64-feat tile, warp = 16 nodes.

__device__ __forceinline__ void ldsm_x4(uint32_t& a0, uint32_t& a1, uint32_t& a2,
                                        uint32_t& a3, uint32_t addr) {
    asm volatile("ldmatrix.sync.aligned.m8n8.x4.shared.b16 {%0,%1,%2,%3}, [%4];"
                 : "=r"(a0), "=r"(a1), "=r"(a2), "=r"(a3) : "r"(addr));
}
__device__ __forceinline__ void ldsm_x2t(uint32_t& b0, uint32_t& b1, uint32_t addr) {
    asm volatile("ldmatrix.sync.aligned.m8n8.x2.trans.shared.b16 {%0,%1}, [%2];"
                 : "=r"(b0), "=r"(b1) : "r"(addr));
}
__device__ __forceinline__ void mma_bf16(float* c, uint32_t a0, uint32_t a1,
                                         uint32_t a2, uint32_t a3,
                                         uint32_t b0, uint32_t b1) {
    asm volatile(
        "mma.sync.aligned.m16n8k16.row.col.f32.bf16.bf16.f32 "
        "{%0,%1,%2,%3},{%4,%5,%6,%7},{%8,%9},{%0,%1,%2,%3};"
        : "+f"(c[0]), "+f"(c[1]), "+f"(c[2]), "+f"(c[3])
        : "r"(a0), "r"(a1), "r"(a2), "r"(a3), "r"(b0), "r"(b1));
}

template <int K, bool SCALE, bool F32SRC>
__global__ void __launch_bounds__(128)
gemm_kernel(const void* __restrict__ Xv, const float* __restrict__ W,
            __nv_bfloat162* __restrict__ Hs) {
    __shared__ __align__(16) __nv_bfloat16 Xs[64][XP];
    __shared__ __align__(16) __nv_bfloat16 Wh[K][XP];
    __shared__ __align__(16) __nv_bfloat16 Wl[K][XP];

    int tid  = threadIdx.x;
    int wp   = tid >> 5;
    int lane = tid & 31;
    int m0   = blockIdx.x * 64;

    // stage W as hi+lo bf16
    for (int i = tid; i < K * 16; i += 128) {   // K*64/4 float4 groups
        int k = (i * 4) >> 6;
        int n = (i * 4) & 63;
        float4 wv = *reinterpret_cast<const float4*>(&W[k * 64 + n]);
        __nv_bfloat16 h0 = __float2bfloat16(wv.x);
        __nv_bfloat16 h1 = __float2bfloat16(wv.y);
        __nv_bfloat16 h2 = __float2bfloat16(wv.z);
        __nv_bfloat16 h3 = __float2bfloat16(wv.w);
        Wh[k][n + 0] = h0; Wh[k][n + 1] = h1; Wh[k][n + 2] = h2; Wh[k][n + 3] = h3;
        Wl[k][n + 0] = __float2bfloat16(wv.x - __bfloat162float(h0));
        Wl[k][n + 1] = __float2bfloat16(wv.y - __bfloat162float(h1));
        Wl[k][n + 2] = __float2bfloat16(wv.z - __bfloat162float(h2));
        Wl[k][n + 3] = __float2bfloat16(wv.w - __bfloat162float(h3));
    }

    float c[8][4];
#pragma unroll
    for (int a = 0; a < 8; a++)
#pragma unroll
        for (int b = 0; b < 4; b++) c[a][b] = 0.f;

    uint32_t xs_b = (uint32_t)__cvta_generic_to_shared(&Xs[0][0]);
    uint32_t wh_b = (uint32_t)__cvta_generic_to_shared(&Wh[0][0]);
    uint32_t wl_b = (uint32_t)__cvta_generic_to_shared(&Wl[0][0]);

    for (int kc = 0; kc < K; kc += 64) {
        // stage 64-node x 64-k chunk of A into Xs (bf16)
        if (F32SRC) {
            const float* X = (const float*)Xv;
#pragma unroll
            for (int l = 0; l < 8; l++) {
                int idx = l * 128 + tid;           // 1024 float4 groups
                int row = idx >> 4;
                int q   = idx & 15;
                int m   = m0 + row;
                float4 v = make_float4(0.f, 0.f, 0.f, 0.f);
                if (m < N_NODES)
                    v = *reinterpret_cast<const float4*>(&X[(size_t)m * K + kc + q * 4]);
                *reinterpret_cast<__nv_bfloat162*>(&Xs[row][q * 4]) =
                    __float22bfloat162_rn(make_float2(v.x, v.y));
                *reinterpret_cast<__nv_bfloat162*>(&Xs[row][q * 4 + 2]) =
                    __float22bfloat162_rn(make_float2(v.z, v.w));
            }
        } else {
            const __nv_bfloat16* X = (const __nv_bfloat16*)Xv;
#pragma unroll
            for (int l = 0; l < 4; l++) {
                int idx = l * 128 + tid;           // 512 uint4 groups
                int row = idx >> 3;
                int q   = idx & 7;
                int m   = m0 + row;
                uint4 v = make_uint4(0u, 0u, 0u, 0u);
                if (m < N_NODES)
                    v = *reinterpret_cast<const uint4*>(&X[(size_t)m * K + kc + q * 8]);
                *reinterpret_cast<uint4*>(&Xs[row][q * 8]) = v;
            }
        }
        __syncthreads();

#pragma unroll
        for (int ks = 0; ks < 4; ks++) {
            uint32_t a0, a1, a2, a3;
            int ar = wp * 16 + (lane & 15);
            int ak = ks * 16 + (lane >> 4) * 8;
            ldsm_x4(a0, a1, a2, a3, xs_b + (ar * XP + ak) * 2);
            int kg = kc + ks * 16 + (lane & 15);
#pragma unroll
            for (int nt = 0; nt < 8; nt++) {
                uint32_t b0, b1;
                ldsm_x2t(b0, b1, wh_b + (kg * XP + nt * 8) * 2);
                mma_bf16(c[nt], a0, a1, a2, a3, b0, b1);
                ldsm_x2t(b0, b1, wl_b + (kg * XP + nt * 8) * 2);
                mma_bf16(c[nt], a0, a1, a2, a3, b0, b1);
            }
        }
        __syncthreads();
    }

    // epilogue: c0,c1 -> row g, cols nt*8+tig*2..+1 ; c2,c3 -> row g+8
    int gid = lane >> 2, tig = lane & 3;
    int r0 = m0 + wp * 16 + gid;
    int r1 = r0 + 8;
    if (r0 < N_NODES) {
        float dv = SCALE ? g_dinv[r0] : 1.0f;
#pragma unroll
        for (int nt = 0; nt < 8; nt++)
            Hs[(size_t)r0 * 32 + nt * 4 + tig] =
                __float22bfloat162_rn(make_float2(c[nt][0] * dv, c[nt][1] * dv));
    }
    if (r1 < N_NODES) {
        float dv = SCALE ? g_dinv[r1] : 1.0f;
#pragma unroll
        for (int nt = 0; nt < 8; nt++)
            Hs[(size_t)r1 * 32 + nt * 4 + tig] =
                __float22bfloat162_rn(make_float2(c[nt][2] * dv, c[nt][3] * dv));
    }
}

// multiply bf16 rows by dinv[v] (applied after gemm1, which runs before dinv exists)
__global__ void __launch_bounds__(256)
scale_kernel(__nv_bfloat162* __restrict__ Hs) {
    int idx = blockIdx.x * 256 + threadIdx.x;
    int v = idx >> 5;
    if (v >= N_NODES) return;
    float dv = g_dinv[v];
    float2 f = __bfloat1622float2(Hs[idx]);
    Hs[idx] = __float22bfloat162_rn(make_float2(f.x * dv, f.y * dv));
}

// ------- fused: CSR gather-aggregate + self-loop + bias + LN + ReLU ---------
__device__ __forceinline__ void agg_node(
    int v, int lane, const __nv_bfloat162* __restrict__ H2,
    const float* __restrict__ bias, const float* __restrict__ lnw,
    const float* __restrict__ lnb, float& y0o, float& y1o) {
    int beg = g_off[v], end = g_off[v + 1];

    float ax = 0.f, ay = 0.f;
    int e = beg;
    for (; e + 4 <= end; e += 4) {
        int s0 = g_src[e], s1 = g_src[e + 1], s2 = g_src[e + 2], s3 = g_src[e + 3];
        float2 h0 = __bfloat1622float2(H2[(size_t)s0 * 32 + lane]);
        float2 h1 = __bfloat1622float2(H2[(size_t)s1 * 32 + lane]);
        float2 h2 = __bfloat1622float2(H2[(size_t)s2 * 32 + lane]);
        float2 h3 = __bfloat1622float2(H2[(size_t)s3 * 32 + lane]);
        ax += (h0.x + h1.x) + (h2.x + h3.x);
        ay += (h0.y + h1.y) + (h2.y + h3.y);
    }
    for (; e < end; e++) {
        int s = g_src[e];
        float2 h = __bfloat1622float2(H2[(size_t)s * 32 + lane]);
        ax += h.x; ay += h.y;
    }

    float dv = g_dinv[v];
    float2 hs = __bfloat1622float2(H2[(size_t)v * 32 + lane]);
    ax = (ax + hs.x) * dv + bias[lane * 2 + 0];
    ay = (ay + hs.y) * dv + bias[lane * 2 + 1];

    float sum = ax + ay;
    float sq  = ax * ax + ay * ay;
#pragma unroll
    for (int o = 16; o > 0; o >>= 1) {
        sum += __shfl_xor_sync(0xffffffffu, sum, o);
        sq  += __shfl_xor_sync(0xffffffffu, sq,  o);
    }
    float mu  = sum * (1.f / 64.f);
    float var = sq * (1.f / 64.f) - mu * mu;
    float r   = rsqrtf(var + 1e-5f);
    float t0 = (ax - mu) * r * lnw[lane * 2 + 0] + lnb[lane * 2 + 0];
    float t1 = (ay - mu) * r * lnw[lane * 2 + 1] + lnb[lane * 2 + 1];
    y0o = fmaxf(t0, 0.f);
    y1o = fmaxf(t1, 0.f);
}

// writes bf16 activations (consumed by tensor-core gemm2/3)
__global__ void __launch_bounds__(256)
agg_ln_kernel(const __nv_bfloat162* __restrict__ H2, const float* __restrict__ bias,
              const float* __restrict__ lnw, const float* __restrict__ lnb,
              __nv_bfloat162* __restrict__ Xo) {
    int v = (blockIdx.x * 256 + threadIdx.x) >> 5;
    int lane = threadIdx.x & 31;
    if (v >= N_NODES) return;
    float y0, y1;
    agg_node(v, lane, H2, bias, lnw, lnb, y0, y1);
    Xo[(size_t)v * 32 + lane] = __float22bfloat162_rn(make_float2(y0, y1));
}

// layer 3: never materialize activations; accumulate the mean-pool directly
#define POOL_BLOCKS 1184
__global__ void __launch_bounds__(256)
agg_ln_pool_kernel(const __nv_bfloat162* __restrict__ H2, const float* __restrict__ bias,
                   const float* __restrict__ lnw, const float* __restrict__ lnb) {
    __shared__ float shp[8 * 64];
    int w    = threadIdx.x >> 5;
    int lane = threadIdx.x & 31;
    int gw   = blockIdx.x * 8 + w;
    const int nw = POOL_BLOCKS * 8;

    float px = 0.f, py = 0.f;
    for (int v = gw; v < N_NODES; v += nw) {
        float y0, y1;
        agg_node(v, lane, H2, bias, lnw, lnb, y0, y1);
        px += y0; py += y1;
    }
    shp[w * 64 + lane * 2 + 0] = px;
    shp[w * 64 + lane * 2 + 1] = py;
    __syncthreads();
    if (threadIdx.x < 64) {
        float s = 0.f;
#pragma unroll
        for (int k = 0; k < 8; k++) s += shp[k * 64 + threadIdx.x];
        atomicAdd(&g_s.pool[threadIdx.x], s);
    }
}

__global__ void final_kernel(const float* __restrict__ Wl, const float* __restrict__ bl,
                             float* __restrict__ out) {
    int o = threadIdx.x;
    if (o < OUT_F) {
        float s = 0.f;
#pragma unroll
        for (int j = 0; j < HID; j++) s += g_s.pool[j] * Wl[j * OUT_F + o];
        out[o] = s * (1.0f / N_NODES) + bl[o];
    }
}

// ---------------- launch ----------------------------------------------------
extern "C" void kernel_launch(void* const* d_in, const int* in_sizes, int n_in,
                              void* d_out, int out_size) {
    const float* x    = (const float*)d_in[0];
    const int*   ei   = (const int*)  d_in[1];
    const float* W1   = (const float*)d_in[2];
    const float* b1   = (const float*)d_in[3];
    const float* W2   = (const float*)d_in[4];
    const float* b2   = (const float*)d_in[5];
    const float* W3   = (const float*)d_in[6];
    const float* b3   = (const float*)d_in[7];
    const float* ln1w = (const float*)d_in[8];
    const float* ln1b = (const float*)d_in[9];
    const float* ln2w = (const float*)d_in[10];
    const float* ln2b = (const float*)d_in[11];
    const float* ln3w = (const float*)d_in[12];
    const float* ln3b = (const float*)d_in[13];
    const float* Wl   = (const float*)d_in[14];
    const float* bl   = (const float*)d_in[15];
    float* out = (float*)d_out;

    const int4* row4 = (const int4*)(ei);             // edge_index[0]
    const int4* col4 = (const int4*)(ei + E_EDGES);   // edge_index[1]

    __nv_bfloat162* gh = nullptr; cudaGetSymbolAddress((void**)&gh, g_h);
    __nv_bfloat162* gx = nullptr; cudaGetSymbolAddress((void**)&gx, g_x);
    void*           gs = nullptr; cudaGetSymbolAddress(&gs, g_s);

    int eB4 = (E_EDGES / 4 + 255) / 256;    // 1563
    int gB  = (N_NODES + 63) / 64;          // 1563 (64-node tiles)
    int aB  = (N_NODES * 32 + 255) / 256;   // 12500 (warp/node)

    // fork a side stream for gemm1 (independent of the CSR build)
    cudaStream_t s;
    cudaStreamCreateWithFlags(&s, cudaStreamNonBlocking);
    cudaEvent_t eFork, eDinv, eJoin;
    cudaEventCreateWithFlags(&eFork, cudaEventDisableTiming);
    cudaEventCreateWithFlags(&eDinv, cudaEventDisableTiming);
    cudaEventCreateWithFlags(&eJoin, cudaEventDisableTiming);

    // ---- main stream: CSR build ----
    cudaMemsetAsync(gs, 0, sizeof(Scratch), 0);   // count + scan state + pool
    cudaEventRecord(eFork, 0);
    count_kernel<<<eB4, 256>>>(col4);
    scan_fused_kernel<<<NCHUNK, 256>>>();
    cudaEventRecord(eDinv, 0);
    scatter_kernel<<<eB4, 256>>>(row4, col4);

    // ---- side stream: gemm1 (no dinv), then dinv scale once dinv is ready --
    cudaStreamWaitEvent(s, eFork, 0);
    gemm_kernel<IN_C, false, true><<<gB, 128, 0, s>>>(x, W1, gh);
    cudaStreamWaitEvent(s, eDinv, 0);
    scale_kernel<<<aB, 256, 0, s>>>(gh);
    cudaEventRecord(eJoin, s);
    cudaStreamWaitEvent(0, eJoin, 0);

    // ---- join: layers sequential from here ----
    agg_ln_kernel<<<aB, 256>>>(gh, b1, ln1w, ln1b, gx);
    gemm_kernel<HID, true, false><<<gB, 128>>>(gx, W2, gh);
    agg_ln_kernel<<<aB, 256>>>(gh, b2, ln2w, ln2b, gx);
    gemm_kernel<HID, true, false><<<gB, 128>>>(gx, W3, gh);
    agg_ln_pool_kernel<<<POOL_BLOCKS, 256>>>(gh, b3, ln3w, ln3b);
    final_kernel<<<1, 32>>>(Wl, bl, out);

    cudaStreamDestroy(s);
    cudaEventDestroy(eFork);
    cudaEventDestroy(eDinv);
    cudaEventDestroy(eJoin);
}